// round 6
// baseline (speedup 1.0000x reference)
#include <cuda_runtime.h>
#include <math.h>

// Problem constants (fixed by the dataset)
#define NGB 16          // graphs
#define NN  2048        // nodes per graph
#define NTT 32768       // total nodes
#define CIN 64
#define HID 128
#define KC  32
#define EDG 524288      // total edges
#define EPG 32768       // edges per graph
#define GN_EPS 1e-5f
#define SELU_SCALE 1.0507009873554805f
#define SELU_ALPHA 1.6732632423543772f

// ---------------- scratch (device globals; no allocation allowed) ----------------
__device__ __align__(16) float g_sum[NGB * CIN];
__device__ __align__(16) float g_sumsq[NGB * CIN];
__device__ int   g_indeg[NTT];                 // in-degree (excl self loop)
__device__ int   g_odeg[NTT];                  // out-degree (adj degrees)
__device__ int   g_rowptr[NTT];                // CSR row start (global edge idx)
__device__ int   g_csrsrc[EDG];                // CSR: src node per slot
__device__ __align__(16) float g_dinv[NTT];
__device__ __align__(16) float g_hw[NTT * HID];   // dinv * (graphnorm(x) @ w1)
__device__ __align__(16) float g_xd[NTT * HID];   // selu(agg+b1)
__device__ __align__(16) float g_s[NTT * KC];     // aligned copy of s
__device__ float g_tr[NGB];                       // trace(out_adj)
__device__ float g_ca[NGB * KC];
__device__ float g_cs[NGB * KC];
__device__ __align__(16) float g_ss[NGB * KC * KC];
__device__ __align__(16) float g_outacc[NGB * KC * HID];

__device__ __forceinline__ float selu_f(float v) {
    return v > 0.f ? SELU_SCALE * v : SELU_SCALE * SELU_ALPHA * (expf(v) - 1.f);
}

// ---------------- kernels ----------------

// per-graph everything: degree hists, block scan -> CSR rowptr, CSR scatter,
// dinv, GraphNorm moments, zeroing of accumulators.  grid = 16 blocks x 1024.
__global__ void __launch_bounds__(1024) prep_k(const int* __restrict__ ei,
                                               const float* __restrict__ x) {
    __shared__ int hin[NN];     // 8 KB
    __shared__ int hout[NN];    // 8 KB
    __shared__ int cur[NN];     // 8 KB
    __shared__ int wsum[32];
    __shared__ float red[2][16][64];   // 8 KB
    int g = blockIdx.x, t = threadIdx.x;

    for (int i = t; i < NN; i += 1024) { hin[i] = 0; hout[i] = 0; }
    __syncthreads();

    const int* srcs = ei + (size_t)g * EPG;
    const int* dsts = ei + EDG + (size_t)g * EPG;
    for (int i = t; i < EPG; i += 1024) {
        atomicAdd(&hout[srcs[i] & (NN - 1)], 1);
        atomicAdd(&hin[dsts[i] & (NN - 1)], 1);
    }

    // GraphNorm moments (same block, independent smem region)
    {
        int c = t & 63, rp = t >> 6;          // 16 row phases
        float s = 0.f, q = 0.f;
        const float* xb = x + (size_t)g * NN * CIN;
        for (int r = rp; r < NN; r += 16) {
            float v = xb[r * CIN + c];
            s += v; q += v * v;
        }
        red[0][rp][c] = s; red[1][rp][c] = q;
    }
    __syncthreads();
    if (t < 64) {
        float ss = 0.f, qq = 0.f;
#pragma unroll
        for (int i = 0; i < 16; i++) { ss += red[0][i][t]; qq += red[1][i][t]; }
        g_sum[g * 64 + t] = ss;
        g_sumsq[g * 64 + t] = qq;
    }

    // exclusive scan of hin (2048 entries, 2 per thread)
    int v0 = hin[2 * t], v1 = hin[2 * t + 1];
    int ps = v0 + v1;
    int lane = t & 31, wp = t >> 5;
    int xs = ps;
#pragma unroll
    for (int o = 1; o < 32; o <<= 1) {
        int y = __shfl_up_sync(0xffffffffu, xs, o);
        if (lane >= o) xs += y;
    }
    if (lane == 31) wsum[wp] = xs;
    __syncthreads();
    if (t < 32) {
        int v = wsum[t];
        int y = v;
#pragma unroll
        for (int o = 1; o < 32; o <<= 1) {
            int z = __shfl_up_sync(0xffffffffu, y, o);
            if (t >= o) y += z;
        }
        wsum[t] = y - v;   // exclusive across warps
    }
    __syncthreads();
    int ex = wsum[wp] + xs - ps;   // exclusive prefix for element 2t
    cur[2 * t] = ex;
    cur[2 * t + 1] = ex + v0;
    int n0 = g * NN + 2 * t;
    int ebase = g * EPG;
    g_rowptr[n0] = ebase + ex;
    g_rowptr[n0 + 1] = ebase + ex + v0;
    g_indeg[n0] = v0;
    g_indeg[n0 + 1] = v1;
    g_odeg[n0] = hout[2 * t];
    g_odeg[n0 + 1] = hout[2 * t + 1];
    g_dinv[n0] = rsqrtf((float)v0 + 1.f);
    g_dinv[n0 + 1] = rsqrtf((float)v1 + 1.f);

    // zero per-graph accumulators
    for (int i = t; i < KC * HID; i += 1024) g_outacc[g * KC * HID + i] = 0.f;
    if (t < KC * KC) g_ss[g * KC * KC + t] = 0.f;
    if (t < KC) { g_ca[g * KC + t] = 0.f; g_cs[g * KC + t] = 0.f; }
    if (t == 0) g_tr[g] = 0.f;
    __syncthreads();

    // CSR scatter (shared-memory cursors)
    for (int i = t; i < EPG; i += 1024) {
        int s = srcs[i];
        int d = dsts[i] & (NN - 1);
        int pos = atomicAdd(&cur[d], 1);
        g_csrsrc[ebase + pos] = s;
    }
}

// fused GraphNorm + GEMM1 (+ dinv scaling): g_hw = dinv * (graphnorm(x) @ w1)
// grid 512 blocks of 128 threads, grid-stride over 2048 tiles of 16 rows.
__global__ void __launch_bounds__(128) gn_gemm1_k(
    const float* __restrict__ x, const float* __restrict__ gw,
    const float* __restrict__ gb, const float* __restrict__ gms,
    const float* __restrict__ w1)
{
    __shared__ float w1t[HID * (CIN + 4)];   // ~34 KB, w1t[t][c] = w1[c][t]
    __shared__ float A[CIN], S[CIN], Bc[CIN];
    __shared__ float hsh[8][CIN];
    __shared__ float dvs[16];
    int t = threadIdx.x;
    for (int c = 0; c < CIN; c++)
        w1t[t * (CIN + 4) + c] = w1[c * HID + t];

    for (int tile = blockIdx.x; tile < NTT / 16; tile += 512) {
        int row0 = tile * 16;
        int g = row0 >> 11;
        __syncthreads();
        if (t < CIN) {
            float mean = g_sum[g * 64 + t] * (1.f / NN);
            float alpha = gms[t];
            float var = g_sumsq[g * 64 + t] * (1.f / NN) - (2.f * alpha - alpha * alpha) * mean * mean;
            S[t] = gw[t] * rsqrtf(var + GN_EPS);
            A[t] = alpha * mean;
            Bc[t] = gb[t];
        }
        if (t < 16) dvs[t] = g_dinv[row0 + t];
        __syncthreads();
        for (int p = 0; p < 2; p++) {
            int r0 = row0 + p * 8;
#pragma unroll
            for (int i = 0; i < 4; i++) {
                int idx = t + i * 128;
                int rr = idx >> 6, c = idx & 63;
                float v = x[(size_t)(r0 + rr) * CIN + c];
                hsh[rr][c] = (v - A[c]) * S[c] + Bc[c];
            }
            __syncthreads();
            float acc[8];
#pragma unroll
            for (int r = 0; r < 8; r++) acc[r] = 0.f;
#pragma unroll
            for (int c = 0; c < CIN; c += 4) {
                float4 w = *(const float4*)&w1t[t * (CIN + 4) + c];
#pragma unroll
                for (int r = 0; r < 8; r++) {
                    float4 h = *(const float4*)&hsh[r][c];
                    acc[r] += w.x * h.x + w.y * h.y + w.z * h.z + w.w * h.w;
                }
            }
#pragma unroll
            for (int r = 0; r < 8; r++)
                g_hw[(size_t)(r0 + r) * HID + t] = acc[r] * dvs[p * 8 + r];
            __syncthreads();
        }
    }
}

// fused CSR gather + SELU + softmax(xd @ w2 + b2).
// one warp per dst row; 1024 blocks x 8 warps, grid-stride (4 sweeps).
__global__ void __launch_bounds__(256) gxs_k(
    const float* __restrict__ b1, const float* __restrict__ w2,
    const float* __restrict__ b2, float* __restrict__ s_out)
{
    __shared__ float w2t[KC * (HID + 4)];   // ~17 KB, w2t[l][j] = w2[j][l]
    __shared__ float xds[8][HID];
    int t = threadIdx.x, wp = t >> 5, l = t & 31;
    for (int idx = t; idx < KC * HID; idx += 256) {
        int j = idx >> 5, ll = idx & 31;
        w2t[ll * (HID + 4) + j] = w2[idx];
    }
    __syncthreads();

    float4 bv = ((const float4*)b1)[l];
    float bz = b2[l];
    const float4* hw4 = (const float4*)g_hw;

    for (int row = blockIdx.x * 8 + wp; row < NTT; row += 8192) {
        float dd = g_dinv[row];
        float4 acc = hw4[(size_t)row * 32 + l];      // self-loop term p_d
        int start = g_rowptr[row], cnt = g_indeg[row];
        for (int base = 0; base < cnt; base += 32) {
            int n = min(32, cnt - base);
            int idx_l = (base + l < cnt) ? g_csrsrc[start + base + l] : 0;
            for (int i = 0; i < n; i++) {
                int s = __shfl_sync(0xffffffffu, idx_l, i);
                float4 v = hw4[(size_t)s * 32 + l];
                acc.x += v.x; acc.y += v.y; acc.z += v.z; acc.w += v.w;
            }
        }
        float4 xv;
        xv.x = selu_f(acc.x * dd + bv.x);
        xv.y = selu_f(acc.y * dd + bv.y);
        xv.z = selu_f(acc.z * dd + bv.z);
        xv.w = selu_f(acc.w * dd + bv.w);
        ((float4*)g_xd)[(size_t)row * 32 + l] = xv;
        *((float4*)&xds[wp][l * 4]) = xv;
        __syncwarp();

        float z = bz;
#pragma unroll
        for (int j = 0; j < HID; j += 4) {
            float4 xj = *(const float4*)&xds[wp][j];
            float4 wj = *(const float4*)&w2t[l * (HID + 4) + j];
            z += xj.x * wj.x + xj.y * wj.y + xj.z * wj.z + xj.w * wj.w;
        }
        float mx = z;
#pragma unroll
        for (int o = 16; o; o >>= 1) mx = fmaxf(mx, __shfl_xor_sync(0xffffffffu, mx, o));
        float ez = expf(z - mx);
        float sm = ez;
#pragma unroll
        for (int o = 16; o; o >>= 1) sm += __shfl_xor_sync(0xffffffffu, sm, o);
        float sv = ez / sm;
        s_out[(size_t)row * KC + l] = sv;
        g_s[(size_t)row * KC + l] = sv;
        __syncwarp();
    }
}

// per-graph reductions: out = s^T xd, ss = s^T s, ca = s^T deg, cs = s^T 1
// grid = 16 graphs * 16 chunks (128 nodes each), 512 threads
__global__ void __launch_bounds__(512) pool_k() {
    int g = blockIdx.x >> 4;
    int chunk = blockIdx.x & 15;
    int node0 = g * NN + chunk * 128;
    __shared__ float ssh[128 * 32];   // 16 KB
    __shared__ float dsh[128];
    int t = threadIdx.x;
    float4* ssh4 = (float4*)ssh;
    const float4* gs4 = (const float4*)g_s;
    for (int i = t; i < 128 * 8; i += 512) ssh4[i] = gs4[(size_t)node0 * 8 + i];
    if (t < 128) dsh[t] = (float)g_odeg[node0 + t];
    __syncthreads();

    int f = t & 127, kb = t >> 7;      // kb in 0..3 -> k = kb*8 .. kb*8+7
    int k1a = t >> 5;                  // 0..15
    int k2 = t & 31;
    float acc[8];
#pragma unroll
    for (int j = 0; j < 8; j++) acc[j] = 0.f;
    float ss0 = 0.f, ss1 = 0.f, csacc = 0.f, caacc = 0.f;

    for (int n = 0; n < 128; n++) {
        float xvv = g_xd[(size_t)(node0 + n) * HID + f];
        float4 s0 = ssh4[n * 8 + kb * 2];
        float4 s1 = ssh4[n * 8 + kb * 2 + 1];
        acc[0] += s0.x * xvv; acc[1] += s0.y * xvv; acc[2] += s0.z * xvv; acc[3] += s0.w * xvv;
        acc[4] += s1.x * xvv; acc[5] += s1.y * xvv; acc[6] += s1.z * xvv; acc[7] += s1.w * xvv;
        float sv2 = ssh[n * 32 + k2];
        ss0 += ssh[n * 32 + k1a] * sv2;
        ss1 += ssh[n * 32 + k1a + 16] * sv2;
        if (t < 32) { float sv = ssh[n * 32 + t]; csacc += sv; caacc += sv * dsh[n]; }
    }

    float* oa = g_outacc + (size_t)g * KC * HID;
#pragma unroll
    for (int j = 0; j < 8; j++) atomicAdd(&oa[(kb * 8 + j) * HID + f], acc[j]);
    atomicAdd(&g_ss[g * 1024 + t], ss0);          // cell t: (t>>5, t&31)
    atomicAdd(&g_ss[g * 1024 + t + 512], ss1);
    if (t < 32) {
        atomicAdd(&g_cs[g * 32 + t], csacc);
        atomicAdd(&g_ca[g * 32 + t], caacc);
    }
}

// trace(out_adj)[b] via CSR: tr += s[dst] . sum_{src in N(dst)} s[src]
// warp per dst row, lane = cluster channel.
__global__ void __launch_bounds__(256) trace_k() {
    int t = threadIdx.x, wp = t >> 5, l = t & 31;
    for (int row = blockIdx.x * 8 + wp; row < NTT; row += gridDim.x * 8) {
        float sv = g_s[(size_t)row * KC + l];
        float acc = 0.f;
        int start = g_rowptr[row], cnt = g_indeg[row];
        for (int base = 0; base < cnt; base += 32) {
            int n = min(32, cnt - base);
            int idx_l = (base + l < cnt) ? g_csrsrc[start + base + l] : 0;
            for (int i = 0; i < n; i++) {
                int s = __shfl_sync(0xffffffffu, idx_l, i);
                acc += g_s[(size_t)s * KC + l];
            }
        }
        float d = acc * sv;
#pragma unroll
        for (int o = 16; o; o >>= 1) d += __shfl_xor_sync(0xffffffffu, d, o);
        if (l == 0) atomicAdd(&g_tr[row >> 11], d);
    }
}

// log_softmax(selu(outacc)) over F=128.  grid 512 (b,k) rows, 128 threads.
__global__ void __launch_bounds__(128) out_final_k(float* __restrict__ outp) {
    int r = blockIdx.x;
    int t = threadIdx.x;
    __shared__ float shm[4], shs[4];
    float y = selu_f(g_outacc[(size_t)r * HID + t]);
    float mx = y;
#pragma unroll
    for (int o = 16; o; o >>= 1) mx = fmaxf(mx, __shfl_xor_sync(0xffffffffu, mx, o));
    if ((t & 31) == 0) shm[t >> 5] = mx;
    __syncthreads();
    float mall = fmaxf(fmaxf(shm[0], shm[1]), fmaxf(shm[2], shm[3]));
    float e = expf(y - mall);
    float sm = e;
#pragma unroll
    for (int o = 16; o; o >>= 1) sm += __shfl_xor_sync(0xffffffffu, sm, o);
    if ((t & 31) == 0) shs[t >> 5] = sm;
    __syncthreads();
    float tot = shs[0] + shs[1] + shs[2] + shs[3];
    outp[(size_t)r * HID + t] = y - mall - logf(tot);
}

// scalar loss.  1 block, 16 warps (warp per graph).
__global__ void __launch_bounds__(512) loss_k(float* __restrict__ outp) {
    int w = threadIdx.x >> 5, l = threadIdx.x & 31;
    __shared__ float parts[16];
    // m = 0.5 * sum(out-degrees)
    float dsum = 0.f;
    for (int n = l; n < NN; n += 32) dsum += (float)g_odeg[w * NN + n];
#pragma unroll
    for (int o = 16; o; o >>= 1) dsum += __shfl_xor_sync(0xffffffffu, dsum, o);
    float m = 0.5f * dsum;

    // spectral
    float ca = g_ca[w * 32 + l];
    float cn = ca * ca;
#pragma unroll
    for (int o = 16; o; o >>= 1) cn += __shfl_xor_sync(0xffffffffu, cn, o);
    float norm_tr = cn / (2.f * m);
    float spec = -(g_tr[w] - norm_tr) / (2.f * m);

    // ortho: sqrt(2 - 2*tr(ss)/(||ss||_F * sqrt(K)))
    float sq = 0.f;
    for (int i = l; i < KC * KC; i += 32) { float v = g_ss[w * 1024 + i]; sq += v * v; }
#pragma unroll
    for (int o = 16; o; o >>= 1) sq += __shfl_xor_sync(0xffffffffu, sq, o);
    float fro = sqrtf(sq);
    float dtr = g_ss[w * 1024 + l * 33];   // diag element l
#pragma unroll
    for (int o = 16; o; o >>= 1) dtr += __shfl_xor_sync(0xffffffffu, dtr, o);
    float ortho = sqrtf(fmaxf(2.f - 2.f * dtr / (fro * sqrtf((float)KC)), 0.f));

    // cluster
    float cs = g_cs[w * 32 + l];
    float csn = cs * cs;
#pragma unroll
    for (int o = 16; o; o >>= 1) csn += __shfl_xor_sync(0xffffffffu, csn, o);
    float clus = sqrtf(csn) / (float)NN * sqrtf((float)KC) - 1.f;

    if (l == 0) parts[w] = spec + ortho + clus;
    __syncthreads();
    if (threadIdx.x == 0) {
        float tot = 0.f;
#pragma unroll
        for (int i = 0; i < 16; i++) tot += parts[i];
        outp[NGB * KC * HID] = tot / (float)NGB;   // outp[65536]
    }
}

// ---------------- launch ----------------
extern "C" void kernel_launch(void* const* d_in, const int* in_sizes, int n_in,
                              void* d_out, int out_size) {
    const float *x = 0, *gw = 0, *gb = 0, *gms = 0, *w1 = 0, *b1 = 0, *w2 = 0, *b2 = 0;
    const int *ei = 0;
    int n64 = 0;
    for (int i = 0; i < n_in; i++) {
        int sz = in_sizes[i];
        if (sz == NTT * CIN)       x = (const float*)d_in[i];
        else if (sz == 2 * EDG)    ei = (const int*)d_in[i];
        else if (sz == NTT)        { /* batch, unused (uniform graphs) */ }
        else if (sz == CIN) {
            if (n64 == 0) gw = (const float*)d_in[i];
            else if (n64 == 1) gb = (const float*)d_in[i];
            else gms = (const float*)d_in[i];
            n64++;
        }
        else if (sz == CIN * HID)  w1 = (const float*)d_in[i];
        else if (sz == HID)        b1 = (const float*)d_in[i];
        else if (sz == HID * KC)   w2 = (const float*)d_in[i];
        else if (sz == KC)         b2 = (const float*)d_in[i];
    }
    float* outp = (float*)d_out;
    float* s_out = outp + NGB * KC * HID + 1;   // s at offset 65537

    prep_k<<<NGB, 1024>>>(ei, x);
    gn_gemm1_k<<<512, 128>>>(x, gw, gb, gms, w1);
    gxs_k<<<1024, 256>>>(b1, w2, b2, s_out);
    pool_k<<<NGB * 16, 512>>>();
    trace_k<<<1024, 256>>>();
    out_final_k<<<NGB * KC, 128>>>(outp);
    loss_k<<<1, 512>>>(outp);
}

// round 8
// speedup vs baseline: 1.6796x; 1.6796x over previous
#include <cuda_runtime.h>
#include <math.h>

// Problem constants (fixed by the dataset)
#define NGB 16          // graphs
#define NN  2048        // nodes per graph
#define NTT 32768       // total nodes
#define CIN 64
#define HID 128
#define KC  32
#define EDG 524288      // total edges
#define EPG 32768       // edges per graph
#define GN_EPS 1e-5f
#define SELU_SCALE 1.0507009873554805f
#define SELU_ALPHA 1.6732632423543772f

// ---------------- scratch (device globals; no allocation allowed) ----------------
__device__ __align__(16) float g_sum[NGB * CIN];
__device__ __align__(16) float g_sumsq[NGB * CIN];
__device__ int   g_indeg[NTT];                 // in-degree (excl self loop)
__device__ int   g_odeg[NTT];                  // out-degree (adj degrees)
__device__ int   g_rowptr[NTT];                // CSR row start
__device__ int   g_cursor[NTT];                // scatter cursors
__device__ int   g_csrsrc[EDG];                // CSR: src node per slot
__device__ int   g_bsum[128];                  // scan block sums
__device__ int   g_boff[128];                  // scan block offsets
__device__ __align__(16) float g_dinv[NTT];
__device__ __align__(16) float g_hw[NTT * HID];   // dinv * (graphnorm(x) @ w1)
__device__ __align__(16) float g_xd[NTT * HID];   // selu(agg+b1)
__device__ __align__(16) float g_s[NTT * KC];     // aligned copy of s
__device__ float g_tr[NGB];                       // trace(out_adj)
__device__ float g_ca[NGB * KC];
__device__ float g_cs[NGB * KC];
__device__ __align__(16) float g_ss[NGB * KC * KC];
__device__ __align__(16) float g_outacc[NGB * KC * HID];

__device__ __forceinline__ float selu_f(float v) {
    return v > 0.f ? SELU_SCALE * v : SELU_SCALE * SELU_ALPHA * (expf(v) - 1.f);
}

// ---------------- kernels ----------------

__global__ void zero_k() {
    int i = blockIdx.x * blockDim.x + threadIdx.x;
    int stride = gridDim.x * blockDim.x;
    for (int j = i; j < NTT; j += stride) { g_indeg[j] = 0; g_odeg[j] = 0; }
    for (int j = i; j < NGB * KC * HID; j += stride) g_outacc[j] = 0.f;
    for (int j = i; j < NGB * KC * KC; j += stride) g_ss[j] = 0.f;
    for (int j = i; j < NGB * CIN; j += stride) { g_sum[j] = 0.f; g_sumsq[j] = 0.f; }
    for (int j = i; j < NGB * KC; j += stride) { g_ca[j] = 0.f; g_cs[j] = 0.f; }
    for (int j = i; j < NGB; j += stride) g_tr[j] = 0.f;
}

// per-graph sum & sumsq per channel. grid = NGB*8 blocks of 512.
__global__ void __launch_bounds__(512) gn_stats_k(const float* __restrict__ x) {
    int g = blockIdx.x >> 3;
    int part = blockIdx.x & 7;           // 256 rows per part
    int t = threadIdx.x;
    int c = t & 63, rp = t >> 6;         // 8 row-phases
    float s = 0.f, q = 0.f;
    const float* xb = x + (size_t)g * NN * CIN;
    int r0 = part * 256;
    for (int r = r0 + rp; r < r0 + 256; r += 8) {
        float v = xb[r * CIN + c];
        s += v; q += v * v;
    }
    __shared__ float sh[2][8][64];
    sh[0][rp][c] = s; sh[1][rp][c] = q;
    __syncthreads();
    if (t < 64) {
        float ss = 0.f, qq = 0.f;
#pragma unroll
        for (int i = 0; i < 8; i++) { ss += sh[0][i][t]; qq += sh[1][i][t]; }
        atomicAdd(&g_sum[g * 64 + t], ss);
        atomicAdd(&g_sumsq[g * 64 + t], qq);
    }
}

__global__ void deg_hist_k(const int* __restrict__ ei) {
    int e = blockIdx.x * blockDim.x + threadIdx.x;
    if (e < EDG) {
        atomicAdd(&g_indeg[ei[EDG + e]], 1);   // dst in-degree
        atomicAdd(&g_odeg[ei[e]], 1);          // src out-degree (adj degrees)
    }
}

// ---- hierarchical exclusive scan of g_indeg (32768 = 128 blocks x 256) ----

__global__ void __launch_bounds__(256) scan1_k() {
    int b = blockIdx.x, t = threadIdx.x;
    int i = b * 256 + t;
    int v = g_indeg[i];
    int lane = t & 31, wp = t >> 5;
    int x = v;
#pragma unroll
    for (int o = 1; o < 32; o <<= 1) {
        int y = __shfl_up_sync(0xffffffffu, x, o);
        if (lane >= o) x += y;
    }
    __shared__ int ws[8];
    if (lane == 31) ws[wp] = x;
    __syncthreads();
    if (t == 0) {
        int run = 0;
#pragma unroll
        for (int w = 0; w < 8; w++) { int tmp = ws[w]; ws[w] = run; run += tmp; }
        g_bsum[b] = run;
    }
    __syncthreads();
    g_rowptr[i] = x - v + ws[wp];   // local exclusive prefix
}

__global__ void __launch_bounds__(128) scan2_k() {
    int t = threadIdx.x;
    __shared__ int sh[128];
    int v = g_bsum[t];
    sh[t] = v;
    __syncthreads();
    for (int o = 1; o < 128; o <<= 1) {
        int y = (t >= o) ? sh[t - o] : 0;
        __syncthreads();
        sh[t] += y;
        __syncthreads();
    }
    g_boff[t] = sh[t] - v;
}

__global__ void __launch_bounds__(256) scan3_k() {
    int b = blockIdx.x, t = threadIdx.x;
    int i = b * 256 + t;
    int rp = g_rowptr[i] + g_boff[b];
    g_rowptr[i] = rp;
    g_cursor[i] = rp;
    g_dinv[i] = rsqrtf((float)g_indeg[i] + 1.f);   // +1 self loop
}

// CSR scatter: slot = cursor[dst]++, csrsrc[slot] = src
__global__ void csr_scatter_k(const int* __restrict__ ei) {
    int e = blockIdx.x * blockDim.x + threadIdx.x;
    if (e < EDG) {
        int src = ei[e], dst = ei[EDG + e];
        int pos = atomicAdd(&g_cursor[dst], 1);
        g_csrsrc[pos] = src;
    }
}

// fused GraphNorm + GEMM1 (+ dinv scaling): g_hw = dinv * (graphnorm(x) @ w1)
// grid 512 blocks of 128 threads, grid-stride over 2048 tiles of 16 rows.
__global__ void __launch_bounds__(128) gn_gemm1_k(
    const float* __restrict__ x, const float* __restrict__ gw,
    const float* __restrict__ gb, const float* __restrict__ gms,
    const float* __restrict__ w1)
{
    __shared__ float w1t[HID * (CIN + 4)];   // ~34 KB, w1t[t][c] = w1[c][t]
    __shared__ float A[CIN], S[CIN], Bc[CIN];
    __shared__ float hsh[8][CIN];
    __shared__ float dvs[16];
    int t = threadIdx.x;
    for (int c = 0; c < CIN; c++)
        w1t[t * (CIN + 4) + c] = w1[c * HID + t];

    for (int tile = blockIdx.x; tile < NTT / 16; tile += 512) {
        int row0 = tile * 16;
        int g = row0 >> 11;
        __syncthreads();
        if (t < CIN) {
            float mean = g_sum[g * 64 + t] * (1.f / NN);
            float alpha = gms[t];
            float var = g_sumsq[g * 64 + t] * (1.f / NN) - (2.f * alpha - alpha * alpha) * mean * mean;
            S[t] = gw[t] * rsqrtf(var + GN_EPS);
            A[t] = alpha * mean;
            Bc[t] = gb[t];
        }
        if (t < 16) dvs[t] = g_dinv[row0 + t];
        __syncthreads();
        for (int p = 0; p < 2; p++) {
            int r0 = row0 + p * 8;
#pragma unroll
            for (int i = 0; i < 4; i++) {
                int idx = t + i * 128;
                int rr = idx >> 6, c = idx & 63;
                float v = x[(size_t)(r0 + rr) * CIN + c];
                hsh[rr][c] = (v - A[c]) * S[c] + Bc[c];
            }
            __syncthreads();
            float acc[8];
#pragma unroll
            for (int r = 0; r < 8; r++) acc[r] = 0.f;
#pragma unroll
            for (int c = 0; c < CIN; c += 4) {
                float4 w = *(const float4*)&w1t[t * (CIN + 4) + c];
#pragma unroll
                for (int r = 0; r < 8; r++) {
                    float4 h = *(const float4*)&hsh[r][c];
                    acc[r] += w.x * h.x + w.y * h.y + w.z * h.z + w.w * h.w;
                }
            }
#pragma unroll
            for (int r = 0; r < 8; r++)
                g_hw[(size_t)(r0 + r) * HID + t] = acc[r] * dvs[p * 8 + r];
            __syncthreads();
        }
    }
}

// fused CSR gather + SELU + softmax(xd @ w2 + b2).
// one warp per dst row; 1024 blocks x 8 warps, grid-stride (4 sweeps).
__global__ void __launch_bounds__(256) gxs_k(
    const float* __restrict__ b1, const float* __restrict__ w2,
    const float* __restrict__ b2, float* __restrict__ s_out)
{
    __shared__ float w2t[KC * (HID + 4)];   // ~17 KB, w2t[l][j] = w2[j][l]
    __shared__ float xds[8][HID];
    int t = threadIdx.x, wp = t >> 5, l = t & 31;
    for (int idx = t; idx < KC * HID; idx += 256) {
        int j = idx >> 5, ll = idx & 31;
        w2t[ll * (HID + 4) + j] = w2[idx];
    }
    __syncthreads();

    float4 bv = ((const float4*)b1)[l];
    float bz = b2[l];
    const float4* hw4 = (const float4*)g_hw;

    for (int row = blockIdx.x * 8 + wp; row < NTT; row += 8192) {
        float dd = g_dinv[row];
        float4 acc = hw4[(size_t)row * 32 + l];      // self-loop term p_d
        int start = g_rowptr[row], cnt = g_indeg[row];
        for (int base = 0; base < cnt; base += 32) {
            int n = min(32, cnt - base);
            int idx_l = (base + l < cnt) ? g_csrsrc[start + base + l] : 0;
            for (int i = 0; i < n; i++) {
                int s = __shfl_sync(0xffffffffu, idx_l, i);
                float4 v = hw4[(size_t)s * 32 + l];
                acc.x += v.x; acc.y += v.y; acc.z += v.z; acc.w += v.w;
            }
        }
        float4 xv;
        xv.x = selu_f(acc.x * dd + bv.x);
        xv.y = selu_f(acc.y * dd + bv.y);
        xv.z = selu_f(acc.z * dd + bv.z);
        xv.w = selu_f(acc.w * dd + bv.w);
        ((float4*)g_xd)[(size_t)row * 32 + l] = xv;
        *((float4*)&xds[wp][l * 4]) = xv;
        __syncwarp();

        float z = bz;
#pragma unroll
        for (int j = 0; j < HID; j += 4) {
            float4 xj = *(const float4*)&xds[wp][j];
            float4 wj = *(const float4*)&w2t[l * (HID + 4) + j];
            z += xj.x * wj.x + xj.y * wj.y + xj.z * wj.z + xj.w * wj.w;
        }
        float mx = z;
#pragma unroll
        for (int o = 16; o; o >>= 1) mx = fmaxf(mx, __shfl_xor_sync(0xffffffffu, mx, o));
        float ez = expf(z - mx);
        float sm = ez;
#pragma unroll
        for (int o = 16; o; o >>= 1) sm += __shfl_xor_sync(0xffffffffu, sm, o);
        float sv = ez / sm;
        s_out[(size_t)row * KC + l] = sv;
        g_s[(size_t)row * KC + l] = sv;
        __syncwarp();
    }
}

// per-graph reductions with register tiling: out = s^T xd, ss = s^T s, ca, cs.
// grid = NGB*8 = 128 blocks (256 nodes each), 256 threads.
// Each thread owns an 8k x 4f output tile; xd staged via shared in 64-node subtiles.
__global__ void __launch_bounds__(256) pool_k() {
    __shared__ float xsh[64 * 128];   // 32 KB
    __shared__ float ssh[64 * 32];    // 8 KB
    __shared__ float dsh[64];
    int g = blockIdx.x >> 3;
    int chunk = blockIdx.x & 7;
    int base = g * NN + chunk * 256;
    int t = threadIdx.x;
    int ns = t >> 7;            // 0..1  n-substream
    int tile = t & 127;
    int kb = tile >> 5;         // 0..3 -> k0 = kb*8
    int fb = tile & 31;         // f0 = fb*4
    int k1 = t >> 3;            // 0..31 (ss row)
    int k2g = t & 7;            // ss col group (float4)

    float acc[8][4];
#pragma unroll
    for (int i = 0; i < 8; i++)
#pragma unroll
        for (int j = 0; j < 4; j++) acc[i][j] = 0.f;
    float4 ssacc = make_float4(0.f, 0.f, 0.f, 0.f);
    float caacc = 0.f, csacc = 0.f;

    float4* xsh4 = (float4*)xsh;
    float4* ssh4 = (float4*)ssh;
    const float4* gx4 = (const float4*)g_xd;
    const float4* gs4 = (const float4*)g_s;

    for (int sub = 0; sub < 4; sub++) {
        int n0 = base + sub * 64;
        __syncthreads();
#pragma unroll
        for (int i = 0; i < 8; i++)
            xsh4[t + i * 256] = gx4[(size_t)n0 * 32 + t + i * 256];
#pragma unroll
        for (int i = 0; i < 2; i++)
            ssh4[t + i * 256] = gs4[(size_t)n0 * 8 + t + i * 256];
        if (t < 64) dsh[t] = (float)g_odeg[n0 + t];
        __syncthreads();

        int nb = ns * 32;
#pragma unroll 2
        for (int n = nb; n < nb + 32; n++) {
            float4 xv = xsh4[n * 32 + fb];
            float4 sa = ssh4[n * 8 + kb * 2];
            float4 sb = ssh4[n * 8 + kb * 2 + 1];
            float sk[8] = {sa.x, sa.y, sa.z, sa.w, sb.x, sb.y, sb.z, sb.w};
            float xf[4] = {xv.x, xv.y, xv.z, xv.w};
#pragma unroll
            for (int i = 0; i < 8; i++)
#pragma unroll
                for (int j = 0; j < 4; j++) acc[i][j] += sk[i] * xf[j];
        }

        // ss over all 64 staged nodes (each thread: row k1, cols k2g*4..+3)
#pragma unroll 2
        for (int n = 0; n < 64; n++) {
            float4 s2 = ssh4[n * 8 + k2g];
            float s1v = ssh[n * 32 + k1];
            ssacc.x += s1v * s2.x; ssacc.y += s1v * s2.y;
            ssacc.z += s1v * s2.z; ssacc.w += s1v * s2.w;
        }
        if (t < 32) {
            for (int n = 0; n < 64; n++) {
                float sv = ssh[n * 32 + t];
                csacc += sv;
                caacc += sv * dsh[n];
            }
        }
    }

    float* oa = g_outacc + (size_t)g * KC * HID;
    int k0 = kb * 8, f0 = fb * 4;
#pragma unroll
    for (int i = 0; i < 8; i++)
#pragma unroll
        for (int j = 0; j < 4; j++)
            atomicAdd(&oa[(k0 + i) * HID + f0 + j], acc[i][j]);
    float* sp = g_ss + g * KC * KC + k1 * KC + k2g * 4;
    atomicAdd(sp + 0, ssacc.x);
    atomicAdd(sp + 1, ssacc.y);
    atomicAdd(sp + 2, ssacc.z);
    atomicAdd(sp + 3, ssacc.w);
    if (t < 32) {
        atomicAdd(&g_cs[g * 32 + t], csacc);
        atomicAdd(&g_ca[g * 32 + t], caacc);
    }
}

// trace(out_adj)[b] via CSR: tr += s[dst] . sum_{src in N(dst)} s[src]
// warp per dst row, lane = cluster channel.
__global__ void __launch_bounds__(256) trace_k() {
    int t = threadIdx.x, wp = t >> 5, l = t & 31;
    for (int row = blockIdx.x * 8 + wp; row < NTT; row += gridDim.x * 8) {
        float sv = g_s[(size_t)row * KC + l];
        float acc = 0.f;
        int start = g_rowptr[row], cnt = g_indeg[row];
        for (int base = 0; base < cnt; base += 32) {
            int n = min(32, cnt - base);
            int idx_l = (base + l < cnt) ? g_csrsrc[start + base + l] : 0;
            for (int i = 0; i < n; i++) {
                int s = __shfl_sync(0xffffffffu, idx_l, i);
                acc += g_s[(size_t)s * KC + l];
            }
        }
        float d = acc * sv;
#pragma unroll
        for (int o = 16; o; o >>= 1) d += __shfl_xor_sync(0xffffffffu, d, o);
        if (l == 0) atomicAdd(&g_tr[row >> 11], d);
    }
}

// log_softmax(selu(outacc)) over F=128.  grid 512 (b,k) rows, 128 threads.
__global__ void __launch_bounds__(128) out_final_k(float* __restrict__ outp) {
    int r = blockIdx.x;
    int t = threadIdx.x;
    __shared__ float shm[4], shs[4];
    float y = selu_f(g_outacc[(size_t)r * HID + t]);
    float mx = y;
#pragma unroll
    for (int o = 16; o; o >>= 1) mx = fmaxf(mx, __shfl_xor_sync(0xffffffffu, mx, o));
    if ((t & 31) == 0) shm[t >> 5] = mx;
    __syncthreads();
    float mall = fmaxf(fmaxf(shm[0], shm[1]), fmaxf(shm[2], shm[3]));
    float e = expf(y - mall);
    float sm = e;
#pragma unroll
    for (int o = 16; o; o >>= 1) sm += __shfl_xor_sync(0xffffffffu, sm, o);
    if ((t & 31) == 0) shs[t >> 5] = sm;
    __syncthreads();
    float tot = shs[0] + shs[1] + shs[2] + shs[3];
    outp[(size_t)r * HID + t] = y - mall - logf(tot);
}

// scalar loss.  1 block, 16 warps (warp per graph).
__global__ void __launch_bounds__(512) loss_k(float* __restrict__ outp) {
    int w = threadIdx.x >> 5, l = threadIdx.x & 31;
    __shared__ float parts[16];
    // m = 0.5 * sum(out-degrees)
    float dsum = 0.f;
    for (int n = l; n < NN; n += 32) dsum += (float)g_odeg[w * NN + n];
#pragma unroll
    for (int o = 16; o; o >>= 1) dsum += __shfl_xor_sync(0xffffffffu, dsum, o);
    float m = 0.5f * dsum;

    // spectral
    float ca = g_ca[w * 32 + l];
    float cn = ca * ca;
#pragma unroll
    for (int o = 16; o; o >>= 1) cn += __shfl_xor_sync(0xffffffffu, cn, o);
    float norm_tr = cn / (2.f * m);
    float spec = -(g_tr[w] - norm_tr) / (2.f * m);

    // ortho: sqrt(2 - 2*tr(ss)/(||ss||_F * sqrt(K)))
    float sq = 0.f;
    for (int i = l; i < KC * KC; i += 32) { float v = g_ss[w * 1024 + i]; sq += v * v; }
#pragma unroll
    for (int o = 16; o; o >>= 1) sq += __shfl_xor_sync(0xffffffffu, sq, o);
    float fro = sqrtf(sq);
    float dtr = g_ss[w * 1024 + l * 33];   // diag element l
#pragma unroll
    for (int o = 16; o; o >>= 1) dtr += __shfl_xor_sync(0xffffffffu, dtr, o);
    float ortho = sqrtf(fmaxf(2.f - 2.f * dtr / (fro * sqrtf((float)KC)), 0.f));

    // cluster
    float cs = g_cs[w * 32 + l];
    float csn = cs * cs;
#pragma unroll
    for (int o = 16; o; o >>= 1) csn += __shfl_xor_sync(0xffffffffu, csn, o);
    float clus = sqrtf(csn) / (float)NN * sqrtf((float)KC) - 1.f;

    if (l == 0) parts[w] = spec + ortho + clus;
    __syncthreads();
    if (threadIdx.x == 0) {
        float tot = 0.f;
#pragma unroll
        for (int i = 0; i < 16; i++) tot += parts[i];
        outp[NGB * KC * HID] = tot / (float)NGB;   // outp[65536]
    }
}

// ---------------- launch ----------------
extern "C" void kernel_launch(void* const* d_in, const int* in_sizes, int n_in,
                              void* d_out, int out_size) {
    const float *x = 0, *gw = 0, *gb = 0, *gms = 0, *w1 = 0, *b1 = 0, *w2 = 0, *b2 = 0;
    const int *ei = 0;
    int n64 = 0;
    for (int i = 0; i < n_in; i++) {
        int sz = in_sizes[i];
        if (sz == NTT * CIN)       x = (const float*)d_in[i];
        else if (sz == 2 * EDG)    ei = (const int*)d_in[i];
        else if (sz == NTT)        { /* batch, unused (uniform graphs) */ }
        else if (sz == CIN) {
            if (n64 == 0) gw = (const float*)d_in[i];
            else if (n64 == 1) gb = (const float*)d_in[i];
            else gms = (const float*)d_in[i];
            n64++;
        }
        else if (sz == CIN * HID)  w1 = (const float*)d_in[i];
        else if (sz == HID)        b1 = (const float*)d_in[i];
        else if (sz == HID * KC)   w2 = (const float*)d_in[i];
        else if (sz == KC)         b2 = (const float*)d_in[i];
    }
    float* outp = (float*)d_out;
    float* s_out = outp + NGB * KC * HID + 1;   // s at offset 65537

    zero_k<<<256, 256>>>();
    gn_stats_k<<<NGB * 8, 512>>>(x);
    deg_hist_k<<<EDG / 256, 256>>>(ei);
    scan1_k<<<128, 256>>>();
    scan2_k<<<1, 128>>>();
    scan3_k<<<128, 256>>>();
    gn_gemm1_k<<<512, 128>>>(x, gw, gb, gms, w1);
    csr_scatter_k<<<EDG / 256, 256>>>(ei);
    gxs_k<<<1024, 256>>>(b1, w2, b2, s_out);
    pool_k<<<NGB * 8, 256>>>();
    trace_k<<<1024, 256>>>();
    out_final_k<<<NGB * KC, 128>>>(outp);
    loss_k<<<1, 512>>>(outp);
}

// round 9
// speedup vs baseline: 2.0769x; 1.2365x over previous
#include <cuda_runtime.h>
#include <cuda_fp16.h>
#include <math.h>

// Problem constants (fixed by the dataset)
#define NGB 16          // graphs
#define NN  2048        // nodes per graph
#define NTT 32768       // total nodes
#define CIN 64
#define HID 128
#define KC  32
#define EDG 524288      // total edges
#define EPG 32768       // edges per graph
#define GN_EPS 1e-5f
#define SELU_SCALE 1.0507009873554805f
#define SELU_ALPHA 1.6732632423543772f

// ---------------- scratch (device globals; no allocation allowed) ----------------
__device__ __align__(16) float g_sumP[128 * CIN];    // per (g,part) partial sums
__device__ __align__(16) float g_sumsqP[128 * CIN];
__device__ __align__(16) float g_gnA[NGB * CIN];     // alpha*mean
__device__ __align__(16) float g_gnS[NGB * CIN];     // gw * rsqrt(var+eps)
__device__ int   g_indeg[NTT];
__device__ int   g_odeg[NTT];
__device__ int   g_rowptr[NTT];
__device__ int   g_cursor[NTT];
__device__ int   g_csrsrc[EDG];
__device__ __align__(16) float g_dinv[NTT];
__device__ __align__(16) __half g_hwh[NTT * HID];    // fp16: dinv*(graphnorm(x)@w1)
__device__ __align__(16) float g_xd[NTT * HID];
__device__ __align__(16) float g_s[NTT * KC];
__device__ float g_tr[NGB];
__device__ float g_ca[NGB * KC];
__device__ float g_cs[NGB * KC];
__device__ __align__(16) float g_ss[NGB * KC * KC];
__device__ __align__(16) float g_outacc[NGB * KC * HID];

__device__ __forceinline__ float selu_f(float v) {
    return v > 0.f ? SELU_SCALE * v : SELU_SCALE * SELU_ALPHA * (expf(v) - 1.f);
}

// ---------------- kernels ----------------

// zero the accumulators that receive atomics.  grid 128 x 256.
__global__ void __launch_bounds__(256) zero_k() {
    int i = blockIdx.x * 256 + threadIdx.x;          // 0..32767
    g_indeg[i] = 0;
    g_odeg[i] = 0;
    g_outacc[i] = 0.f;
    g_outacc[i + 32768] = 0.f;
    if (i < NGB * KC * KC) g_ss[i] = 0.f;
    if (i < NGB * KC) { g_ca[i] = 0.f; g_cs[i] = 0.f; }
    if (i < NGB) g_tr[i] = 0.f;
}

// blocks<128: GraphNorm moment partials (no atomics).  blocks>=128: degree hist.
__global__ void __launch_bounds__(512) stats_hist_k(const float* __restrict__ x,
                                                    const int* __restrict__ ei) {
    int b = blockIdx.x, t = threadIdx.x;
    if (b < 128) {
        int g = b >> 3, part = b & 7;
        int c = t & 63, rp = t >> 6;
        float s = 0.f, q = 0.f;
        const float* xb = x + (size_t)g * NN * CIN;
        int r0 = part * 256;
        for (int r = r0 + rp; r < r0 + 256; r += 8) {
            float v = xb[r * CIN + c];
            s += v; q += v * v;
        }
        __shared__ float sh[2][8][64];
        sh[0][rp][c] = s; sh[1][rp][c] = q;
        __syncthreads();
        if (t < 64) {
            float ss = 0.f, qq = 0.f;
#pragma unroll
            for (int i = 0; i < 8; i++) { ss += sh[0][i][t]; qq += sh[1][i][t]; }
            g_sumP[b * 64 + t] = ss;
            g_sumsqP[b * 64 + t] = qq;
        }
    } else {
        int e = (b - 128) * 512 + t;    // 1024 blocks x 512 = EDG
        atomicAdd(&g_indeg[ei[EDG + e]], 1);
        atomicAdd(&g_odeg[ei[e]], 1);
    }
}

// per-graph: finalize GN coefficients + exclusive scan of indeg -> rowptr/cursor/dinv
// grid = 16 blocks x 1024.
__global__ void __launch_bounds__(1024) prep2_k(const float* __restrict__ gw,
                                                const float* __restrict__ gms) {
    __shared__ int wsum[32];
    int g = blockIdx.x, t = threadIdx.x;

    if (t < 64) {
        float ss = 0.f, qq = 0.f;
#pragma unroll
        for (int p = 0; p < 8; p++) {
            ss += g_sumP[(g * 8 + p) * 64 + t];
            qq += g_sumsqP[(g * 8 + p) * 64 + t];
        }
        float mean = ss * (1.f / NN);
        float alpha = gms[t];
        float var = qq * (1.f / NN) - (2.f * alpha - alpha * alpha) * mean * mean;
        g_gnS[g * 64 + t] = gw[t] * rsqrtf(var + GN_EPS);
        g_gnA[g * 64 + t] = alpha * mean;
    }

    int n0 = g * NN + 2 * t;
    int v0 = g_indeg[n0], v1 = g_indeg[n0 + 1];
    int ps = v0 + v1;
    int lane = t & 31, wp = t >> 5;
    int xs = ps;
#pragma unroll
    for (int o = 1; o < 32; o <<= 1) {
        int y = __shfl_up_sync(0xffffffffu, xs, o);
        if (lane >= o) xs += y;
    }
    if (lane == 31) wsum[wp] = xs;
    __syncthreads();
    if (t < 32) {
        int v = wsum[t];
        int y = v;
#pragma unroll
        for (int o = 1; o < 32; o <<= 1) {
            int z = __shfl_up_sync(0xffffffffu, y, o);
            if (t >= o) y += z;
        }
        wsum[t] = y - v;
    }
    __syncthreads();
    int ex = wsum[wp] + xs - ps;
    int ebase = g * EPG;
    g_rowptr[n0] = ebase + ex;
    g_rowptr[n0 + 1] = ebase + ex + v0;
    g_cursor[n0] = ebase + ex;
    g_cursor[n0 + 1] = ebase + ex + v0;
    g_dinv[n0] = rsqrtf((float)v0 + 1.f);
    g_dinv[n0 + 1] = rsqrtf((float)v1 + 1.f);
}

// CSR scatter: slot = cursor[dst]++, csrsrc[slot] = src
__global__ void __launch_bounds__(256) csr_scatter_k(const int* __restrict__ ei) {
    int e = blockIdx.x * 256 + threadIdx.x;
    int src = ei[e], dst = ei[EDG + e];
    int pos = atomicAdd(&g_cursor[dst], 1);
    g_csrsrc[pos] = src;
}

// fused GraphNorm + GEMM1 (+ dinv scaling) -> fp16: g_hwh = dinv*(graphnorm(x)@w1)
// grid 1024 blocks of 128 threads, grid-stride over 2048 tiles of 16 rows.
__global__ void __launch_bounds__(128) gemm1h_k(
    const float* __restrict__ x, const float* __restrict__ gb,
    const float* __restrict__ w1)
{
    __shared__ float w1t[HID * (CIN + 4)];   // ~34 KB
    __shared__ float A[CIN], S[CIN], Bc[CIN];
    __shared__ float hsh[8][CIN];
    __shared__ float dvs[16];
    int t = threadIdx.x;
    for (int c = 0; c < CIN; c++)
        w1t[t * (CIN + 4) + c] = w1[c * HID + t];
    if (t < 64) Bc[t] = gb[t];

    for (int tile = blockIdx.x; tile < NTT / 16; tile += 1024) {
        int row0 = tile * 16;
        int g = row0 >> 11;
        __syncthreads();
        if (t < 64) { A[t] = g_gnA[g * 64 + t]; S[t] = g_gnS[g * 64 + t]; }
        if (t < 16) dvs[t] = g_dinv[row0 + t];
        __syncthreads();
        for (int p = 0; p < 2; p++) {
            int r0 = row0 + p * 8;
#pragma unroll
            for (int i = 0; i < 4; i++) {
                int idx = t + i * 128;
                int rr = idx >> 6, c = idx & 63;
                float v = x[(size_t)(r0 + rr) * CIN + c];
                hsh[rr][c] = (v - A[c]) * S[c] + Bc[c];
            }
            __syncthreads();
            float acc[8];
#pragma unroll
            for (int r = 0; r < 8; r++) acc[r] = 0.f;
#pragma unroll
            for (int c = 0; c < CIN; c += 4) {
                float4 w = *(const float4*)&w1t[t * (CIN + 4) + c];
#pragma unroll
                for (int r = 0; r < 8; r++) {
                    float4 h = *(const float4*)&hsh[r][c];
                    acc[r] += w.x * h.x + w.y * h.y + w.z * h.z + w.w * h.w;
                }
            }
#pragma unroll
            for (int r = 0; r < 8; r++)
                g_hwh[(size_t)(r0 + r) * HID + t] = __float2half(acc[r] * dvs[p * 8 + r]);
            __syncthreads();
        }
    }
}

__device__ __forceinline__ void acc_h4(float4& acc, uint2 u) {
    __half2 ha = *(__half2*)&u.x, hb = *(__half2*)&u.y;
    float2 f0 = __half22float2(ha), f1 = __half22float2(hb);
    acc.x += f0.x; acc.y += f0.y; acc.z += f1.x; acc.w += f1.y;
}

// fused CSR gather (fp16 rows) + SELU + softmax(xd @ w2 + b2).
// one warp per dst row; 1024 blocks x 8 warps, grid-stride (4 sweeps).
__global__ void __launch_bounds__(256) gxsh_k(
    const float* __restrict__ b1, const float* __restrict__ w2,
    const float* __restrict__ b2, float* __restrict__ s_out)
{
    __shared__ float w2t[KC * (HID + 4)];   // ~17 KB
    __shared__ float xds[8][HID];
    int t = threadIdx.x, wp = t >> 5, l = t & 31;
    for (int idx = t; idx < KC * HID; idx += 256) {
        int j = idx >> 5, ll = idx & 31;
        w2t[ll * (HID + 4) + j] = w2[idx];
    }
    __syncthreads();

    float4 bv = ((const float4*)b1)[l];
    float bz = b2[l];
    const uint2* hwp = (const uint2*)g_hwh;   // row stride = 32 uint2 (256B)

    for (int row = blockIdx.x * 8 + wp; row < NTT; row += 8192) {
        float dd = g_dinv[row];
        float4 acc = make_float4(0.f, 0.f, 0.f, 0.f);
        acc_h4(acc, hwp[(size_t)row * 32 + l]);      // self-loop term
        int start = g_rowptr[row], cnt = g_indeg[row];
        for (int base = 0; base < cnt; base += 32) {
            int n = min(32, cnt - base);
            int idx_l = (base + l < cnt) ? g_csrsrc[start + base + l] : 0;
            int i = 0;
            for (; i + 4 <= n; i += 4) {
                int s0 = __shfl_sync(0xffffffffu, idx_l, i);
                int s1 = __shfl_sync(0xffffffffu, idx_l, i + 1);
                int s2 = __shfl_sync(0xffffffffu, idx_l, i + 2);
                int s3 = __shfl_sync(0xffffffffu, idx_l, i + 3);
                uint2 u0 = hwp[(size_t)s0 * 32 + l];
                uint2 u1 = hwp[(size_t)s1 * 32 + l];
                uint2 u2 = hwp[(size_t)s2 * 32 + l];
                uint2 u3 = hwp[(size_t)s3 * 32 + l];
                acc_h4(acc, u0); acc_h4(acc, u1); acc_h4(acc, u2); acc_h4(acc, u3);
            }
            for (; i < n; i++) {
                int s = __shfl_sync(0xffffffffu, idx_l, i);
                acc_h4(acc, hwp[(size_t)s * 32 + l]);
            }
        }
        float4 xv;
        xv.x = selu_f(acc.x * dd + bv.x);
        xv.y = selu_f(acc.y * dd + bv.y);
        xv.z = selu_f(acc.z * dd + bv.z);
        xv.w = selu_f(acc.w * dd + bv.w);
        ((float4*)g_xd)[(size_t)row * 32 + l] = xv;
        *((float4*)&xds[wp][l * 4]) = xv;
        __syncwarp();

        float z = bz;
#pragma unroll
        for (int j = 0; j < HID; j += 4) {
            float4 xj = *(const float4*)&xds[wp][j];
            float4 wj = *(const float4*)&w2t[l * (HID + 4) + j];
            z += xj.x * wj.x + xj.y * wj.y + xj.z * wj.z + xj.w * wj.w;
        }
        float mx = z;
#pragma unroll
        for (int o = 16; o; o >>= 1) mx = fmaxf(mx, __shfl_xor_sync(0xffffffffu, mx, o));
        float ez = expf(z - mx);
        float sm = ez;
#pragma unroll
        for (int o = 16; o; o >>= 1) sm += __shfl_xor_sync(0xffffffffu, sm, o);
        float sv = ez / sm;
        s_out[(size_t)row * KC + l] = sv;
        g_s[(size_t)row * KC + l] = sv;
        __syncwarp();
    }
}

// blocks<128: register-tiled pooled reductions.  blocks>=128: CSR trace.
// grid = 128 + 512 = 640 blocks x 256 threads.
__global__ void __launch_bounds__(256) pool_trace_k() {
    __shared__ float xsh[64 * 128];   // 32 KB
    __shared__ float ssh[64 * 32];    // 8 KB
    __shared__ float dsh[64];
    int t = threadIdx.x;

    if (blockIdx.x < 128) {
        int g = blockIdx.x >> 3;
        int chunk = blockIdx.x & 7;
        int base = g * NN + chunk * 256;
        int ns = t >> 7;
        int tile = t & 127;
        int kb = tile >> 5;
        int fb = tile & 31;
        int k1 = t >> 3;
        int k2g = t & 7;

        float acc[8][4];
#pragma unroll
        for (int i = 0; i < 8; i++)
#pragma unroll
            for (int j = 0; j < 4; j++) acc[i][j] = 0.f;
        float4 ssacc = make_float4(0.f, 0.f, 0.f, 0.f);
        float caacc = 0.f, csacc = 0.f;

        float4* xsh4 = (float4*)xsh;
        float4* ssh4 = (float4*)ssh;
        const float4* gx4 = (const float4*)g_xd;
        const float4* gs4 = (const float4*)g_s;

        for (int sub = 0; sub < 4; sub++) {
            int n0 = base + sub * 64;
            __syncthreads();
#pragma unroll
            for (int i = 0; i < 8; i++)
                xsh4[t + i * 256] = gx4[(size_t)n0 * 32 + t + i * 256];
#pragma unroll
            for (int i = 0; i < 2; i++)
                ssh4[t + i * 256] = gs4[(size_t)n0 * 8 + t + i * 256];
            if (t < 64) dsh[t] = (float)g_odeg[n0 + t];
            __syncthreads();

            int nb = ns * 32;
#pragma unroll 2
            for (int n = nb; n < nb + 32; n++) {
                float4 xv = xsh4[n * 32 + fb];
                float4 sa = ssh4[n * 8 + kb * 2];
                float4 sb = ssh4[n * 8 + kb * 2 + 1];
                float sk[8] = {sa.x, sa.y, sa.z, sa.w, sb.x, sb.y, sb.z, sb.w};
                float xf[4] = {xv.x, xv.y, xv.z, xv.w};
#pragma unroll
                for (int i = 0; i < 8; i++)
#pragma unroll
                    for (int j = 0; j < 4; j++) acc[i][j] += sk[i] * xf[j];
            }

#pragma unroll 2
            for (int n = 0; n < 64; n++) {
                float4 s2 = ssh4[n * 8 + k2g];
                float s1v = ssh[n * 32 + k1];
                ssacc.x += s1v * s2.x; ssacc.y += s1v * s2.y;
                ssacc.z += s1v * s2.z; ssacc.w += s1v * s2.w;
            }
            if (t < 32) {
                for (int n = 0; n < 64; n++) {
                    float sv = ssh[n * 32 + t];
                    csacc += sv;
                    caacc += sv * dsh[n];
                }
            }
        }

        float* oa = g_outacc + (size_t)g * KC * HID;
        int k0 = kb * 8, f0 = fb * 4;
#pragma unroll
        for (int i = 0; i < 8; i++)
#pragma unroll
            for (int j = 0; j < 4; j++)
                atomicAdd(&oa[(k0 + i) * HID + f0 + j], acc[i][j]);
        float* sp = g_ss + g * KC * KC + k1 * KC + k2g * 4;
        atomicAdd(sp + 0, ssacc.x);
        atomicAdd(sp + 1, ssacc.y);
        atomicAdd(sp + 2, ssacc.z);
        atomicAdd(sp + 3, ssacc.w);
        if (t < 32) {
            atomicAdd(&g_cs[g * 32 + t], csacc);
            atomicAdd(&g_ca[g * 32 + t], caacc);
        }
    } else {
        // trace: 512 blocks, warp handles 8 consecutive rows
        int b2 = blockIdx.x - 128;
        int wp = t >> 5, l = t & 31;
        int rbase = b2 * 64 + wp * 8;
        float tracc = 0.f;
        for (int r = 0; r < 8; r++) {
            int row = rbase + r;
            float sv = g_s[(size_t)row * KC + l];
            float acc = 0.f;
            int start = g_rowptr[row], cnt = g_indeg[row];
            for (int base = 0; base < cnt; base += 32) {
                int n = min(32, cnt - base);
                int idx_l = (base + l < cnt) ? g_csrsrc[start + base + l] : 0;
                int i = 0;
                for (; i + 4 <= n; i += 4) {
                    int s0 = __shfl_sync(0xffffffffu, idx_l, i);
                    int s1 = __shfl_sync(0xffffffffu, idx_l, i + 1);
                    int s2 = __shfl_sync(0xffffffffu, idx_l, i + 2);
                    int s3 = __shfl_sync(0xffffffffu, idx_l, i + 3);
                    float v0 = g_s[(size_t)s0 * KC + l];
                    float v1 = g_s[(size_t)s1 * KC + l];
                    float v2 = g_s[(size_t)s2 * KC + l];
                    float v3 = g_s[(size_t)s3 * KC + l];
                    acc += v0 + v1 + v2 + v3;
                }
                for (; i < n; i++) {
                    int s = __shfl_sync(0xffffffffu, idx_l, i);
                    acc += g_s[(size_t)s * KC + l];
                }
            }
            tracc += acc * sv;
        }
#pragma unroll
        for (int o = 16; o; o >>= 1) tracc += __shfl_xor_sync(0xffffffffu, tracc, o);
        if (l == 0) atomicAdd(&g_tr[rbase >> 11], tracc);
    }
}

// blocks<512: log_softmax(selu(outacc)).  block 512: scalar loss.
__global__ void __launch_bounds__(128) final_k(float* __restrict__ outp) {
    int t = threadIdx.x;
    if (blockIdx.x < 512) {
        int r = blockIdx.x;
        __shared__ float shm[4], shs[4];
        float y = selu_f(g_outacc[(size_t)r * HID + t]);
        float mx = y;
#pragma unroll
        for (int o = 16; o; o >>= 1) mx = fmaxf(mx, __shfl_xor_sync(0xffffffffu, mx, o));
        if ((t & 31) == 0) shm[t >> 5] = mx;
        __syncthreads();
        float mall = fmaxf(fmaxf(shm[0], shm[1]), fmaxf(shm[2], shm[3]));
        float e = expf(y - mall);
        float sm = e;
#pragma unroll
        for (int o = 16; o; o >>= 1) sm += __shfl_xor_sync(0xffffffffu, sm, o);
        if ((t & 31) == 0) shs[t >> 5] = sm;
        __syncthreads();
        float tot = shs[0] + shs[1] + shs[2] + shs[3];
        outp[(size_t)r * HID + t] = y - mall - logf(tot);
    } else {
        __shared__ float parts[16];
        int wp = t >> 5, l = t & 31;
        for (int w = wp; w < 16; w += 4) {
            float dsum = 0.f;
            for (int n = l; n < NN; n += 32) dsum += (float)g_odeg[w * NN + n];
#pragma unroll
            for (int o = 16; o; o >>= 1) dsum += __shfl_xor_sync(0xffffffffu, dsum, o);
            float m = 0.5f * dsum;

            float ca = g_ca[w * 32 + l];
            float cn = ca * ca;
#pragma unroll
            for (int o = 16; o; o >>= 1) cn += __shfl_xor_sync(0xffffffffu, cn, o);
            float norm_tr = cn / (2.f * m);
            float spec = -(g_tr[w] - norm_tr) / (2.f * m);

            float sq = 0.f;
            for (int i = l; i < KC * KC; i += 32) { float v = g_ss[w * 1024 + i]; sq += v * v; }
#pragma unroll
            for (int o = 16; o; o >>= 1) sq += __shfl_xor_sync(0xffffffffu, sq, o);
            float fro = sqrtf(sq);
            float dtr = g_ss[w * 1024 + l * 33];
#pragma unroll
            for (int o = 16; o; o >>= 1) dtr += __shfl_xor_sync(0xffffffffu, dtr, o);
            float ortho = sqrtf(fmaxf(2.f - 2.f * dtr / (fro * sqrtf((float)KC)), 0.f));

            float cs = g_cs[w * 32 + l];
            float csn = cs * cs;
#pragma unroll
            for (int o = 16; o; o >>= 1) csn += __shfl_xor_sync(0xffffffffu, csn, o);
            float clus = sqrtf(csn) / (float)NN * sqrtf((float)KC) - 1.f;

            if (l == 0) parts[w] = spec + ortho + clus;
        }
        __syncthreads();
        if (t == 0) {
            float tot = 0.f;
#pragma unroll
            for (int i = 0; i < 16; i++) tot += parts[i];
            outp[NGB * KC * HID] = tot / (float)NGB;
        }
    }
}

// ---------------- launch ----------------
extern "C" void kernel_launch(void* const* d_in, const int* in_sizes, int n_in,
                              void* d_out, int out_size) {
    const float *x = 0, *gw = 0, *gb = 0, *gms = 0, *w1 = 0, *b1 = 0, *w2 = 0, *b2 = 0;
    const int *ei = 0;
    int n64 = 0;
    for (int i = 0; i < n_in; i++) {
        int sz = in_sizes[i];
        if (sz == NTT * CIN)       x = (const float*)d_in[i];
        else if (sz == 2 * EDG)    ei = (const int*)d_in[i];
        else if (sz == NTT)        { /* batch, unused (uniform graphs) */ }
        else if (sz == CIN) {
            if (n64 == 0) gw = (const float*)d_in[i];
            else if (n64 == 1) gb = (const float*)d_in[i];
            else gms = (const float*)d_in[i];
            n64++;
        }
        else if (sz == CIN * HID)  w1 = (const float*)d_in[i];
        else if (sz == HID)        b1 = (const float*)d_in[i];
        else if (sz == HID * KC)   w2 = (const float*)d_in[i];
        else if (sz == KC)         b2 = (const float*)d_in[i];
    }
    float* outp = (float*)d_out;
    float* s_out = outp + NGB * KC * HID + 1;   // s at offset 65537

    zero_k<<<128, 256>>>();
    stats_hist_k<<<128 + 1024, 512>>>(x, ei);
    prep2_k<<<NGB, 1024>>>(gw, gms);
    csr_scatter_k<<<EDG / 256, 256>>>(ei);
    gemm1h_k<<<1024, 128>>>(x, gb, w1);
    gxsh_k<<<1024, 256>>>(b1, w2, b2, s_out);
    pool_trace_k<<<128 + 512, 256>>>();
    final_k<<<513, 128>>>(outp);
}